// round 4
// baseline (speedup 1.0000x reference)
#include <cuda_runtime.h>

#define DNUM 20
#define ONUM 19
#define MNUM 32
#define MM   (MNUM * MNUM)
#define NROWS (ONUM * ONUM * ONUM)        // 6859 (a,b,c) rows
#define ROWF  (DNUM * MNUM)               // 640 floats per row slab

typedef unsigned long long u64;

// C[k][i][j] = cos(2*pi*k / (32*i + j + 2)), k in [0,19)
__device__ __align__(16) float g_C[ONUM * MM];
// H3[abc][d'][k]: 3-axis neighbor sums (keep d', k)
__device__ __align__(16) float g_H3[NROWS * ROWF];
// XT[abc][j][d]: windowed, M-transformed, transposed; d padded to 20 (d=19 -> 0)
__device__ __align__(16) float g_XT[NROWS * ROWF];

__device__ __forceinline__ u64 ffma2(u64 a, u64 b, u64 c) {
    u64 d;
    asm("fma.rn.f32x2 %0, %1, %2, %3;" : "=l"(d) : "l"(a), "l"(b), "l"(c));
    return d;
}
__device__ __forceinline__ u64 pk2(float lo, float hi) {
    u64 r;
    asm("mov.b64 %0, {%1, %2};" : "=l"(r) : "f"(lo), "f"(hi));
    return r;
}
__device__ __forceinline__ void upk2(u64 v, float& lo, float& hi) {
    asm("mov.b64 {%0, %1}, %2;" : "=f"(lo), "=f"(hi) : "l"(v));
}

__global__ void init_tabs() {
    int t = blockIdx.x * blockDim.x + threadIdx.x;
    if (t < ONUM * MM) {
        int k = t / MM;
        int r = t % MM;                  // r = i*32 + j, period = r + 2
        g_C[t] = cosf(6.283185307179586f * (float)k / (float)(r + 2));
    }
}

// k1: H3[abc][d'][k] = sum over {da,db,dc} of h[a+da, b+db, c+dc, d', k]  (float4)
__global__ __launch_bounds__(160) void k1_h3(const float* __restrict__ h) {
    const int abc = blockIdx.x;
    const int c = abc % ONUM;
    const int t = abc / ONUM;
    const int b = t % ONUM, a = t / ONUM;
    const float4* base = (const float4*)(h + ((a * DNUM + b) * DNUM + c) * ROWF)
                       + threadIdx.x;
    // float4 offsets: dc:+160, db:+3200, da:+64000
    float4 r0 = __ldg(base);
    float4 r1 = __ldg(base + 160);
    float4 r2 = __ldg(base + 3200);
    float4 r3 = __ldg(base + 3360);
    float4 r4 = __ldg(base + 64000);
    float4 r5 = __ldg(base + 64160);
    float4 r6 = __ldg(base + 67200);
    float4 r7 = __ldg(base + 67360);
    float4 o;
    o.x = ((r0.x + r1.x) + (r2.x + r3.x)) + ((r4.x + r5.x) + (r6.x + r7.x));
    o.y = ((r0.y + r1.y) + (r2.y + r3.y)) + ((r4.y + r5.y) + (r6.y + r7.y));
    o.z = ((r0.z + r1.z) + (r2.z + r3.z)) + ((r4.z + r5.z) + (r6.z + r7.z));
    o.w = ((r0.w + r1.w) + (r2.w + r3.w)) + ((r4.w + r5.w) + (r6.w + r7.w));
    ((float4*)g_H3)[abc * 160 + threadIdx.x] = o;
}

// k2: per row, 20 matvecs x_j(d') = sum_k M[j,k]*H3[row,d',k], then window over d'
// and write transposed XT[row][j][d] (d padded to 20, last = 0).
#define K2W 8
__global__ __launch_bounds__(K2W * 32) void k2_matvec(const float* __restrict__ Mw) {
    __shared__ float sT[K2W][MNUM * 21];
    const int w = threadIdx.x >> 5, lane = threadIdx.x & 31;  // lane = j
    const int row = blockIdx.x * K2W + w;
    if (row >= NROWS) return;

    float Mr[MNUM];
    {
        const float4* M4 = (const float4*)Mw + lane * 8;
#pragma unroll
        for (int v = 0; v < 8; ++v) {
            float4 m = __ldg(M4 + v);
            Mr[4*v+0] = m.x; Mr[4*v+1] = m.y; Mr[4*v+2] = m.z; Mr[4*v+3] = m.w;
        }
    }
    float xw[DNUM];
    const float4* H4 = (const float4*)(g_H3 + row * ROWF);
#pragma unroll
    for (int dp = 0; dp < DNUM; ++dp) {
        float a0 = 0.f, a1 = 0.f, a2 = 0.f, a3 = 0.f;
#pragma unroll
        for (int v = 0; v < 8; ++v) {
            float4 hv = __ldg(H4 + dp * 8 + v);   // uniform across lanes
            a0 = fmaf(Mr[4*v+0], hv.x, a0);
            a1 = fmaf(Mr[4*v+1], hv.y, a1);
            a2 = fmaf(Mr[4*v+2], hv.z, a2);
            a3 = fmaf(Mr[4*v+3], hv.w, a3);
        }
        xw[dp] = (a0 + a1) + (a2 + a3);
    }
    // window mean over d' and transpose via smem (stride 21 -> conflict-free STS)
#pragma unroll
    for (int d = 0; d < ONUM; ++d)
        sT[w][lane * 21 + d] = (xw[d] + xw[d + 1]) * 0.0625f;
    sT[w][lane * 21 + 19] = 0.0f;
    __syncwarp();
    float4* o4 = (float4*)(g_XT + row * ROWF);
#pragma unroll
    for (int e = lane; e < 160; e += 32) {
        int f0 = e * 4;
        int j0 = f0 / 20, d0 = f0 % 20;        // 20 % 4 == 0: never crosses a j row
        float4 v;
        v.x = sT[w][j0 * 21 + d0 + 0];
        v.y = sT[w][j0 * 21 + d0 + 1];
        v.z = sT[w][j0 * 21 + d0 + 2];
        v.w = sT[w][j0 * 21 + d0 + 3];
        o4[e] = v;
    }
}

// main: per warp-row, lane = i. j outer, packed Chebyshev double-step inner.
#define WPB 8
__global__ __launch_bounds__(WPB * 32, 2)
void sdd_main(const float* __restrict__ P, float* __restrict__ out) {
    const int w = threadIdx.x >> 5, lane = threadIdx.x & 31;
    const int row = blockIdx.x * WPB + w;
    if (row >= NROWS) return;

    const int a = row / (ONUM * ONUM);
    const int bc = row - a * (ONUM * ONUM);
    const int b = bc / ONUM;
    const int c = bc - b * ONUM;

    // Per-lane (lane = i): tc1[j] = 2*cos(theta_ij); uu[j] = (P.*Ca.*Cb.*Cc)[i,j]
    float tc1[MNUM], uu[MNUM];
    {
        const float4* T4 = (const float4*)(g_C + MM) + lane * 8;   // k=1 slab
        const float4* P4 = (const float4*)P + lane * 8;
        const float4* A4 = (const float4*)g_C + a * (MM / 4) + lane * 8;
        const float4* B4 = (const float4*)g_C + b * (MM / 4) + lane * 8;
        const float4* C4 = (const float4*)g_C + c * (MM / 4) + lane * 8;
#pragma unroll
        for (int v4 = 0; v4 < 8; ++v4) {
            float4 tv = __ldg(T4 + v4);
            float4 pv = __ldg(P4 + v4), av = __ldg(A4 + v4);
            float4 bv = __ldg(B4 + v4), cv = __ldg(C4 + v4);
            tc1[4*v4+0] = 2.0f * tv.x; tc1[4*v4+1] = 2.0f * tv.y;
            tc1[4*v4+2] = 2.0f * tv.z; tc1[4*v4+3] = 2.0f * tv.w;
            uu[4*v4+0] = pv.x * av.x * bv.x * cv.x;
            uu[4*v4+1] = pv.y * av.y * bv.y * cv.y;
            uu[4*v4+2] = pv.z * av.z * bv.z * cv.z;
            uu[4*v4+3] = pv.w * av.w * bv.w * cv.w;
        }
    }

    u64 acc[10];
#pragma unroll
    for (int k = 0; k < 10; ++k) acc[k] = 0ull;

    const ulonglong2* xr = (const ulonglong2*)(g_XT + row * ROWF);

#pragma unroll 2
    for (int j = 0; j < MNUM; ++j) {
        const float tc = tc1[j];
        const float csq = tc * tc;
        const u64 tc2  = pk2(csq - 2.0f, csq - 2.0f);   // 2cos(2theta)
        const u64 ntc2 = pk2(2.0f - csq, 2.0f - csq);
        const float t0 = uu[j];
        const float t1 = 0.5f * tc * t0;
        const float t2 = fmaf(tc, t1, -t0);
        const float t3 = fmaf(tc, t2, -t1);

        ulonglong2 xa = __ldg(xr + j * 5 + 0);   // d pairs 0,1
        ulonglong2 xb = __ldg(xr + j * 5 + 1);   // 2,3
        ulonglong2 xc = __ldg(xr + j * 5 + 2);   // 4,5
        ulonglong2 xd = __ldg(xr + j * 5 + 3);   // 6,7
        ulonglong2 xe = __ldg(xr + j * 5 + 4);   // 8,9

        u64 s0 = pk2(t0, t1);                    //  p0
        u64 s1 = pk2(t2, t3);                    //  p1
        acc[0] = ffma2(xa.x, s0, acc[0]);
        acc[1] = ffma2(xa.y, s1, acc[1]);
        u64 s2 = ffma2(ntc2, s1, s0);            // -p2
        acc[2] = ffma2(xb.x, s2, acc[2]);
        u64 s3 = ffma2(tc2, s2, s1);             // -p3
        acc[3] = ffma2(xb.y, s3, acc[3]);
        s0 = ffma2(ntc2, s3, s2);                //  p4
        acc[4] = ffma2(xc.x, s0, acc[4]);
        s1 = ffma2(tc2, s0, s3);                 //  p5
        acc[5] = ffma2(xc.y, s1, acc[5]);
        s2 = ffma2(ntc2, s1, s0);                // -p6
        acc[6] = ffma2(xd.x, s2, acc[6]);
        s3 = ffma2(tc2, s2, s1);                 // -p7
        acc[7] = ffma2(xd.y, s3, acc[7]);
        s0 = ffma2(ntc2, s3, s2);                //  p8
        acc[8] = ffma2(xe.x, s0, acc[8]);
        s1 = ffma2(tc2, s0, s3);                 //  p9
        acc[9] = ffma2(xe.y, s1, acc[9]);
    }

    // epilogue: pairs k -> d = 2k, 2k+1; k mod 4 in {2,3} (bit1 set) were negated
    float* op = out + row * (ONUM * MNUM) + lane;
#pragma unroll
    for (int k = 0; k < 10; ++k) {
        float lo, hi;
        upk2(acc[k], lo, hi);
        const float s = (k & 2) ? -1.0f : 1.0f;
        op[(2 * k) * MNUM] = s * lo;
        if (2 * k + 1 < ONUM) op[(2 * k + 1) * MNUM] = s * hi;
    }
}

extern "C" void kernel_launch(void* const* d_in, const int* in_sizes, int n_in,
                              void* d_out, int out_size) {
    const float* h  = (const float*)d_in[0];   // hypervol [20,20,20,20,32]
    const float* Mw = (const float*)d_in[1];   // M_w [32,32]
    const float* P  = (const float*)d_in[2];   // P  [32,32]
    float* out = (float*)d_out;                // [130321, 32]

    init_tabs<<<(ONUM * MM + 511) / 512, 512>>>();
    k1_h3<<<NROWS, 160>>>(h);
    k2_matvec<<<(NROWS + K2W - 1) / K2W, K2W * 32>>>(Mw);
    sdd_main<<<(NROWS + WPB - 1) / WPB, WPB * 32>>>(P, out);
}

// round 5
// speedup vs baseline: 1.4213x; 1.4213x over previous
#include <cuda_runtime.h>

#define DNUM 20
#define ONUM 19
#define MNUM 32
#define MM   1024
#define NAB  (ONUM * ONUM)                // 361
#define NROWS (ONUM * ONUM * ONUM)        // 6859
#define ROWF  (DNUM * MNUM)               // 640

typedef unsigned long long u64;

// transposed tables: CT[k][j][i] = cos(2*pi*k/(32*i+j+2)), PT[j][i] = P[i][j]
__device__ __align__(16) float g_CT[ONUM * MM];
__device__ __align__(16) float g_PT[MM];
__device__ __align__(16) float g_G[NAB * MM];     // G[ab][j][i] = PT * CTa * CTb
__device__ __align__(16) float g_XT[NROWS * ROWF]; // [row][j][d(20, last=0)]

__device__ __forceinline__ u64 ffma2(u64 a, u64 b, u64 c) {
    u64 d;
    asm("fma.rn.f32x2 %0, %1, %2, %3;" : "=l"(d) : "l"(a), "l"(b), "l"(c));
    return d;
}
__device__ __forceinline__ u64 pk2(float lo, float hi) {
    u64 r;
    asm("mov.b64 %0, {%1, %2};" : "=l"(r) : "f"(lo), "f"(hi));
    return r;
}
__device__ __forceinline__ void upk2(u64 v, float& lo, float& hi) {
    asm("mov.b64 {%0, %1}, %2;" : "=f"(lo), "=f"(hi) : "l"(v));
}

__global__ void init_tabs(const float* __restrict__ P) {
    int t = blockIdx.x * blockDim.x + threadIdx.x;
    if (t < ONUM * MM) {
        int k = t / MM, r = t % MM;
        int j = r >> 5, i = r & 31;
        g_CT[t] = cosf(6.283185307179586f * (float)k / (float)(i * MNUM + j + 2));
    } else if (t < ONUM * MM + MM) {
        int e = t - ONUM * MM;                    // e = j*32 + i
        g_PT[e] = P[(e & 31) * MNUM + (e >> 5)];
    }
}

__global__ __launch_bounds__(256) void k_gab() {
    const int ab = blockIdx.x;
    const int a = ab / ONUM, b = ab % ONUM;
    const int e = threadIdx.x;                    // 256 float4 per slab
    float4 p = ((const float4*)g_PT)[e];
    float4 av = ((const float4*)(g_CT + a * MM))[e];
    float4 bv = ((const float4*)(g_CT + b * MM))[e];
    float4 o;
    o.x = p.x * av.x * bv.x;
    o.y = p.y * av.y * bv.y;
    o.z = p.z * av.z * bv.z;
    o.w = p.w * av.w * bv.w;
    ((float4*)(g_G + ab * MM))[e] = o;
}

// Fused: H3 (3-axis neighbor sums) in smem -> matvec by M -> window over d -> XT
#define K12T 160
__global__ __launch_bounds__(K12T) void k12(const float* __restrict__ h,
                                            const float* __restrict__ Mw) {
    __shared__ __align__(16) float sH[ROWF];
    __shared__ float sXdp[DNUM][MNUM];

    const int abc = blockIdx.x;
    const int c = abc % ONUM;
    const int t2 = abc / ONUM;
    const int b = t2 % ONUM, a = t2 / ONUM;

    // phase 1: H3 slab (640 floats) into smem, one float4 per thread
    {
        const float4* base = (const float4*)(h + ((a * DNUM + b) * DNUM + c) * ROWF)
                           + threadIdx.x;
        float4 r0 = __ldg(base),          r1 = __ldg(base + 160);
        float4 r2 = __ldg(base + 3200),   r3 = __ldg(base + 3360);
        float4 r4 = __ldg(base + 64000),  r5 = __ldg(base + 64160);
        float4 r6 = __ldg(base + 67200),  r7 = __ldg(base + 67360);
        float4 o;
        o.x = ((r0.x + r1.x) + (r2.x + r3.x)) + ((r4.x + r5.x) + (r6.x + r7.x));
        o.y = ((r0.y + r1.y) + (r2.y + r3.y)) + ((r4.y + r5.y) + (r6.y + r7.y));
        o.z = ((r0.z + r1.z) + (r2.z + r3.z)) + ((r4.z + r5.z) + (r6.z + r7.z));
        o.w = ((r0.w + r1.w) + (r2.w + r3.w)) + ((r4.w + r5.w) + (r6.w + r7.w));
        ((float4*)sH)[threadIdx.x] = o;
    }
    __syncthreads();

    // phase 2: x_j(d') = sum_k M[j,k]*H3[d',k]; 5 warps x 4 d' each, lane = j
    const int w = threadIdx.x >> 5, lane = threadIdx.x & 31;
    {
        float Mr[MNUM];
        const float4* M4 = (const float4*)Mw + lane * 8;
#pragma unroll
        for (int v = 0; v < 8; ++v) {
            float4 m = __ldg(M4 + v);
            Mr[4*v+0] = m.x; Mr[4*v+1] = m.y; Mr[4*v+2] = m.z; Mr[4*v+3] = m.w;
        }
        const float4* H4 = (const float4*)sH;
#pragma unroll
        for (int q = 0; q < 4; ++q) {
            const int dp = w + 5 * q;
            float a0 = 0.f, a1 = 0.f, a2 = 0.f, a3 = 0.f;
#pragma unroll
            for (int v = 0; v < 8; ++v) {
                float4 hv = H4[dp * 8 + v];      // uniform LDS -> broadcast
                a0 = fmaf(Mr[4*v+0], hv.x, a0);
                a1 = fmaf(Mr[4*v+1], hv.y, a1);
                a2 = fmaf(Mr[4*v+2], hv.z, a2);
                a3 = fmaf(Mr[4*v+3], hv.w, a3);
            }
            sXdp[dp][lane] = (a0 + a1) + (a2 + a3);
        }
    }
    __syncthreads();

    // phase 3: window over d, transpose to [j][d(20)], one float4 per thread
    {
        const int e = threadIdx.x;
        const int f0 = e * 4;
        const int j0 = f0 / 20, d0 = f0 % 20;    // 20 % 4 == 0: stays within one j
        float q[4];
#pragma unroll
        for (int t = 0; t < 4; ++t) {
            const int d = d0 + t;
            q[t] = (d < ONUM) ? (sXdp[d][j0] + sXdp[d + 1][j0]) * 0.0625f : 0.0f;
        }
        float4 v; v.x = q[0]; v.y = q[1]; v.z = q[2]; v.w = q[3];
        ((float4*)(g_XT + abc * ROWF))[e] = v;
    }
}

// main: warp per row, lane = i; j outer with table reload, packed Chebyshev inner
#define WPB 4
__global__ __launch_bounds__(WPB * 32, 6)
void sdd_main(float* __restrict__ out) {
    __shared__ __align__(16) float sX[WPB][ROWF];

    const int w = threadIdx.x >> 5, lane = threadIdx.x & 31;
    const int row = blockIdx.x * WPB + w;
    if (row >= NROWS) return;

    const int a = row / NAB;
    const int bc = row - a * NAB;
    const int b = bc / ONUM;
    const int c = bc - b * ONUM;
    const int ab = a * ONUM + b;

    // stage this row's XT slab (2560B) into smem
    {
        const float4* xr4 = (const float4*)(g_XT + row * ROWF);
        float4* s4 = (float4*)sX[w];
#pragma unroll
        for (int q = 0; q < 5; ++q)
            s4[lane + 32 * q] = __ldg(xr4 + lane + 32 * q);
    }
    __syncwarp();

    const float* Gp = g_G + ab * MM + lane;       // (P*Ca*Cb)^T
    const float* Cc = g_CT + c * MM + lane;       // Cc^T
    const float* C1 = g_CT + MM + lane;           // cos(theta)^T
    const ulonglong2* xs = (const ulonglong2*)sX[w];

    u64 acc[10];
#pragma unroll
    for (int k = 0; k < 10; ++k) acc[k] = 0ull;

#pragma unroll 2
    for (int j = 0; j < MNUM; ++j) {
        const float tc = 2.0f * __ldg(C1 + j * MNUM);
        const float u0 = __ldg(Gp + j * MNUM) * __ldg(Cc + j * MNUM);
        const float csq = tc * tc;
        const u64 tc2  = pk2(csq - 2.0f, csq - 2.0f);   // 2cos(2theta)
        const u64 ntc2 = pk2(2.0f - csq, 2.0f - csq);
        const float t1 = 0.5f * tc * u0;
        const float t2 = fmaf(tc, t1, -u0);
        const float t3 = fmaf(tc, t2, -t1);

        ulonglong2 xa = xs[j * 5 + 0];   // d pairs 0,1
        ulonglong2 xb = xs[j * 5 + 1];   // 2,3
        ulonglong2 xc = xs[j * 5 + 2];   // 4,5
        ulonglong2 xd = xs[j * 5 + 3];   // 6,7
        ulonglong2 xe = xs[j * 5 + 4];   // 8,9

        u64 s0 = pk2(u0, t1);                    //  p0
        u64 s1 = pk2(t2, t3);                    //  p1
        acc[0] = ffma2(xa.x, s0, acc[0]);
        acc[1] = ffma2(xa.y, s1, acc[1]);
        u64 s2 = ffma2(ntc2, s1, s0);            // -p2
        acc[2] = ffma2(xb.x, s2, acc[2]);
        u64 s3 = ffma2(tc2, s2, s1);             // -p3
        acc[3] = ffma2(xb.y, s3, acc[3]);
        s0 = ffma2(ntc2, s3, s2);                //  p4
        acc[4] = ffma2(xc.x, s0, acc[4]);
        s1 = ffma2(tc2, s0, s3);                 //  p5
        acc[5] = ffma2(xc.y, s1, acc[5]);
        s2 = ffma2(ntc2, s1, s0);                // -p6
        acc[6] = ffma2(xd.x, s2, acc[6]);
        s3 = ffma2(tc2, s2, s1);                 // -p7
        acc[7] = ffma2(xd.y, s3, acc[7]);
        s0 = ffma2(ntc2, s3, s2);                //  p8
        acc[8] = ffma2(xe.x, s0, acc[8]);
        s1 = ffma2(tc2, s0, s3);                 //  p9
        acc[9] = ffma2(xe.y, s1, acc[9]);
    }

    // epilogue: pair k -> d = 2k, 2k+1; k mod 4 in {2,3} were negated
    float* op = out + row * (ONUM * MNUM) + lane;
#pragma unroll
    for (int k = 0; k < 10; ++k) {
        float lo, hi;
        upk2(acc[k], lo, hi);
        const float s = (k & 2) ? -1.0f : 1.0f;
        op[(2 * k) * MNUM] = s * lo;
        if (2 * k + 1 < ONUM) op[(2 * k + 1) * MNUM] = s * hi;
    }
}

extern "C" void kernel_launch(void* const* d_in, const int* in_sizes, int n_in,
                              void* d_out, int out_size) {
    const float* h  = (const float*)d_in[0];   // hypervol [20,20,20,20,32]
    const float* Mw = (const float*)d_in[1];   // M_w [32,32]
    const float* P  = (const float*)d_in[2];   // P  [32,32]
    float* out = (float*)d_out;                // [130321, 32]

    init_tabs<<<(ONUM * MM + MM + 511) / 512, 512>>>(P);
    k_gab<<<NAB, 256>>>();
    k12<<<NROWS, K12T>>>(h, Mw);
    sdd_main<<<(NROWS + WPB - 1) / WPB, WPB * 32>>>(out);
}